// round 1
// baseline (speedup 1.0000x reference)
#include <cuda_runtime.h>

#define NN   50000
#define NE   600000
#define INF  602
#define HID  128
#define OUTF 41

// ---------------- scratch (static device globals; no allocs allowed) --------
__device__ float g_h  [NN * HID];
__device__ float g_agg[NN * HID];
__device__ float g_x1 [NN * HID];
__device__ float g_x2 [NN * HID];
__device__ float g_x3 [NN * HID];
__device__ float g_deg_out[NN];
__device__ float g_deg_in [NN];
__device__ float g_rout[NN];
__device__ float g_rin [NN];

// ---------------- degree computation ----------------------------------------
__global__ void deg_kernel(const int* __restrict__ src, const int* __restrict__ dst,
                           float* __restrict__ dout, float* __restrict__ din, int ne) {
    int i = blockIdx.x * blockDim.x + threadIdx.x;
    if (i < ne) {
        atomicAdd(&dout[src[i]], 1.0f);
        atomicAdd(&din [dst[i]], 1.0f);
    }
}

__global__ void rinv_kernel(const float* __restrict__ dout, const float* __restrict__ din,
                            float* __restrict__ rout, float* __restrict__ rin, int n) {
    int i = blockIdx.x * blockDim.x + threadIdx.x;
    if (i < n) {
        rout[i] = rsqrtf(fmaxf(dout[i], 1.0f));
        rin [i] = rsqrtf(fmaxf(din [i], 1.0f));
    }
}

// ---------------- scaled GEMM: C[M,128] = diag(rinv) * A[M,K] @ W[K,128] -----
#define BM 64
#define BN 128
#define BK 8
#define TM 4
#define TN 8

__global__ void __launch_bounds__(256)
gemm_scaled_kernel(const float* __restrict__ A, const float* __restrict__ W,
                   const float* __restrict__ rinv, float* __restrict__ C,
                   int M, int K) {
    __shared__ float As[BK][BM];
    __shared__ float Bs[BK][BN];

    const int block_row = blockIdx.x * BM;
    const int tid = threadIdx.x;          // 256 threads
    const int tx  = tid & 15;             // N direction (16 * TN = 128)
    const int ty  = tid >> 4;             // M direction (16 * TM = 64)

    // A-tile load mapping: 64x8 = 512 elems, 2 per thread
    const int a_r0 = tid >> 3;            // 0..31
    const int a_k0 = tid & 7;
    const int gr0 = block_row + a_r0;
    const int gr1 = gr0 + 32;
    const float s0 = (gr0 < M) ? rinv[gr0] : 0.0f;
    const float s1 = (gr1 < M) ? rinv[gr1] : 0.0f;

    float acc[TM][TN];
#pragma unroll
    for (int i = 0; i < TM; ++i)
#pragma unroll
        for (int j = 0; j < TN; ++j) acc[i][j] = 0.0f;

    for (int k0 = 0; k0 < K; k0 += BK) {
        // load A (row-scaled)
        {
            int gk = k0 + a_k0;
            float v0 = 0.0f, v1 = 0.0f;
            if (gk < K) {
                if (gr0 < M) v0 = A[(long)gr0 * K + gk] * s0;
                if (gr1 < M) v1 = A[(long)gr1 * K + gk] * s1;
            }
            As[a_k0][a_r0]      = v0;
            As[a_k0][a_r0 + 32] = v1;
        }
        // load W tile: 8x128 = 1024 elems, 4 per thread, coalesced over cols
#pragma unroll
        for (int j = 0; j < 4; ++j) {
            int i = tid + j * 256;
            int r = i >> 7, c = i & 127;
            int gk = k0 + r;
            Bs[r][c] = (gk < K) ? W[(long)gk * BN + c] : 0.0f;
        }
        __syncthreads();

#pragma unroll
        for (int kk = 0; kk < BK; ++kk) {
            float4 ra  = *reinterpret_cast<const float4*>(&As[kk][ty * TM]);
            float4 rb0 = *reinterpret_cast<const float4*>(&Bs[kk][tx * TN]);
            float4 rb1 = *reinterpret_cast<const float4*>(&Bs[kk][tx * TN + 4]);
            float a_[TM] = {ra.x, ra.y, ra.z, ra.w};
            float b_[TN] = {rb0.x, rb0.y, rb0.z, rb0.w, rb1.x, rb1.y, rb1.z, rb1.w};
#pragma unroll
            for (int i = 0; i < TM; ++i)
#pragma unroll
                for (int j = 0; j < TN; ++j)
                    acc[i][j] += a_[i] * b_[j];
        }
        __syncthreads();
    }

#pragma unroll
    for (int i = 0; i < TM; ++i) {
        int gr = block_row + ty * TM + i;
        if (gr < M) {
#pragma unroll
            for (int j = 0; j < TN; j += 4) {
                float4 v = make_float4(acc[i][j], acc[i][j+1], acc[i][j+2], acc[i][j+3]);
                *reinterpret_cast<float4*>(&C[(long)gr * BN + tx * TN + j]) = v;
            }
        }
    }
}

// ---------------- edge scatter: agg[dst] += h[src]  (warp per edge) ---------
__global__ void scatter_kernel(const float* __restrict__ h, const int* __restrict__ src,
                               const int* __restrict__ dst, float* __restrict__ agg, int ne) {
    int gtid = blockIdx.x * blockDim.x + threadIdx.x;
    int e    = gtid >> 5;
    int lane = gtid & 31;
    if (e >= ne) return;
    int s = src[e], d = dst[e];
    float4 v = reinterpret_cast<const float4*>(h + (long)s * HID)[lane];
    float* ap = agg + (long)d * HID + lane * 4;
    atomicAdd(ap + 0, v.x);
    atomicAdd(ap + 1, v.y);
    atomicAdd(ap + 2, v.z);
    atomicAdd(ap + 3, v.w);
}

// ---------------- epilogue: x = relu(agg * rsqrt(deg_in) + b) ---------------
__global__ void finalize_kernel(const float* __restrict__ agg, const float* __restrict__ rin,
                                const float* __restrict__ b, float* __restrict__ out, int n4) {
    int i = blockIdx.x * blockDim.x + threadIdx.x;
    if (i >= n4) return;
    float4 a = reinterpret_cast<const float4*>(agg)[i];
    int base = i * 4;
    int node = base / HID;
    int col  = base % HID;
    float r = rin[node];
    float4 o;
    o.x = fmaxf(fmaf(a.x, r, b[col + 0]), 0.0f);
    o.y = fmaxf(fmaf(a.y, r, b[col + 1]), 0.0f);
    o.z = fmaxf(fmaf(a.z, r, b[col + 2]), 0.0f);
    o.w = fmaxf(fmaf(a.w, r, b[col + 3]), 0.0f);
    reinterpret_cast<float4*>(out)[i] = o;
}

// ---------------- FC head: out = relu(x3 + x2) @ Wfc + bfc ------------------
__global__ void __launch_bounds__(128)
fc_kernel(const float* __restrict__ x3, const float* __restrict__ x2,
          const float* __restrict__ Wfc, const float* __restrict__ bfc,
          float* __restrict__ out) {
    __shared__ float y[HID];
    int n = blockIdx.x;
    int t = threadIdx.x;  // 128
    y[t] = fmaxf(x3[(long)n * HID + t] + x2[(long)n * HID + t], 0.0f);
    __syncthreads();
    if (t < OUTF) {
        float acc = bfc[t];
#pragma unroll 16
        for (int k = 0; k < HID; ++k)
            acc = fmaf(y[k], Wfc[k * OUTF + t], acc);
        out[(long)n * OUTF + t] = acc;
    }
}

// ---------------- launcher ---------------------------------------------------
extern "C" void kernel_launch(void* const* d_in, const int* in_sizes, int n_in,
                              void* d_out, int out_size) {
    const float* feat = (const float*)d_in[0];
    const int*   src  = (const int*)  d_in[1];
    const int*   dst  = (const int*)  d_in[2];
    const float* W1   = (const float*)d_in[3];
    const float* b1   = (const float*)d_in[4];
    const float* W2   = (const float*)d_in[5];
    const float* b2   = (const float*)d_in[6];
    const float* W3   = (const float*)d_in[7];
    const float* b3   = (const float*)d_in[8];
    const float* Wfc  = (const float*)d_in[9];
    const float* bfc  = (const float*)d_in[10];
    float* out = (float*)d_out;

    float *h, *agg, *x1, *x2, *x3, *dout, *din, *rout, *rin;
    cudaGetSymbolAddress((void**)&h,    g_h);
    cudaGetSymbolAddress((void**)&agg,  g_agg);
    cudaGetSymbolAddress((void**)&x1,   g_x1);
    cudaGetSymbolAddress((void**)&x2,   g_x2);
    cudaGetSymbolAddress((void**)&x3,   g_x3);
    cudaGetSymbolAddress((void**)&dout, g_deg_out);
    cudaGetSymbolAddress((void**)&din,  g_deg_in);
    cudaGetSymbolAddress((void**)&rout, g_rout);
    cudaGetSymbolAddress((void**)&rin,  g_rin);

    const int nfeat4 = NN * HID / 4;

    // degrees (graph-structure only; shared by all layers)
    cudaMemsetAsync(dout, 0, NN * sizeof(float));
    cudaMemsetAsync(din,  0, NN * sizeof(float));
    deg_kernel<<<(NE + 255) / 256, 256>>>(src, dst, dout, din, NE);
    rinv_kernel<<<(NN + 255) / 256, 256>>>(dout, din, rout, rin, NN);

    const int gemm_grid    = (NN + BM - 1) / BM;
    const int scatter_grid = (NE * 32 + 255) / 256;
    const int fin_grid     = (nfeat4 + 255) / 256;

    // layer 1: 602 -> 128
    gemm_scaled_kernel<<<gemm_grid, 256>>>(feat, W1, rout, h, NN, INF);
    cudaMemsetAsync(agg, 0, (size_t)NN * HID * sizeof(float));
    scatter_kernel<<<scatter_grid, 256>>>(h, src, dst, agg, NE);
    finalize_kernel<<<fin_grid, 256>>>(agg, rin, b1, x1, nfeat4);

    // layer 2: 128 -> 128   (note: reference computes this twice; results are
    // identical, so x2 serves as both the main path and the residual branch)
    gemm_scaled_kernel<<<gemm_grid, 256>>>(x1, W2, rout, h, NN, HID);
    cudaMemsetAsync(agg, 0, (size_t)NN * HID * sizeof(float));
    scatter_kernel<<<scatter_grid, 256>>>(h, src, dst, agg, NE);
    finalize_kernel<<<fin_grid, 256>>>(agg, rin, b2, x2, nfeat4);

    // layer 3: 128 -> 128
    gemm_scaled_kernel<<<gemm_grid, 256>>>(x2, W3, rout, h, NN, HID);
    cudaMemsetAsync(agg, 0, (size_t)NN * HID * sizeof(float));
    scatter_kernel<<<scatter_grid, 256>>>(h, src, dst, agg, NE);
    finalize_kernel<<<fin_grid, 256>>>(agg, rin, b3, x3, nfeat4);

    // FC head with fused residual relu
    fc_kernel<<<NN, 128>>>(x3, x2, Wfc, bfc, out);
}

// round 2
// speedup vs baseline: 2.0755x; 2.0755x over previous
#include <cuda_runtime.h>

#define NN   50000
#define NE   600000
#define INF  602
#define HID  128
#define OUTF 41

// ---------------- scratch (static device globals; no allocs allowed) --------
__device__ float g_h  [NN * HID];
__device__ float g_x1 [NN * HID];
__device__ float g_x2 [NN * HID];
__device__ float g_x3 [NN * HID];
__device__ int   g_cnt_out[NN];
__device__ int   g_cnt_in [NN];
__device__ int   g_cursor [NN];
__device__ int   g_row_start[NN + 1];
__device__ int   g_esrc[NE];
__device__ float g_rout[NN];
__device__ float g_rin [NN];

// ---------------- degree counting -------------------------------------------
__global__ void count_kernel(const int* __restrict__ src, const int* __restrict__ dst,
                             int* __restrict__ cout, int* __restrict__ cin, int ne) {
    int i = blockIdx.x * blockDim.x + threadIdx.x;
    if (i < ne) {
        atomicAdd(&cout[src[i]], 1);
        atomicAdd(&cin [dst[i]], 1);
    }
}

__global__ void rinv_kernel(const int* __restrict__ cout, const int* __restrict__ cin,
                            float* __restrict__ rout, float* __restrict__ rin, int n) {
    int i = blockIdx.x * blockDim.x + threadIdx.x;
    if (i < n) {
        rout[i] = rsqrtf(fmaxf((float)cout[i], 1.0f));
        rin [i] = rsqrtf(fmaxf((float)cin [i], 1.0f));
    }
}

// ---------------- exclusive prefix sum over cnt_in (single block) -----------
__global__ void __launch_bounds__(1024)
scan_kernel(const int* __restrict__ cnt, int* __restrict__ row_start) {
    __shared__ int warp_sums[32];
    __shared__ int s_carry;
    int tid  = threadIdx.x;
    int lane = tid & 31, wid = tid >> 5;
    if (tid == 0) s_carry = 0;
    __syncthreads();
    for (int base = 0; base < NN; base += 1024) {
        int i = base + tid;
        int v = (i < NN) ? cnt[i] : 0;
        int x = v;
#pragma unroll
        for (int off = 1; off < 32; off <<= 1) {
            int t = __shfl_up_sync(0xffffffffu, x, off);
            if (lane >= off) x += t;
        }
        if (lane == 31) warp_sums[wid] = x;
        __syncthreads();
        if (wid == 0) {
            int w = warp_sums[lane];
#pragma unroll
            for (int off = 1; off < 32; off <<= 1) {
                int t = __shfl_up_sync(0xffffffffu, w, off);
                if (lane >= off) w += t;
            }
            warp_sums[lane] = w;
        }
        __syncthreads();
        int warp_off = (wid == 0) ? 0 : warp_sums[wid - 1];
        int carry = s_carry;
        if (i < NN) row_start[i] = carry + warp_off + x - v;
        __syncthreads();
        if (tid == 1023) s_carry = carry + warp_sums[31];
        __syncthreads();
    }
    if (tid == 0) row_start[NN] = NE;
}

// ---------------- CSR fill ---------------------------------------------------
__global__ void fill_kernel(const int* __restrict__ src, const int* __restrict__ dst,
                            const int* __restrict__ row_start, int* __restrict__ cursor,
                            int* __restrict__ esrc, int ne) {
    int i = blockIdx.x * blockDim.x + threadIdx.x;
    if (i < ne) {
        int d = dst[i];
        int pos = row_start[d] + atomicAdd(&cursor[d], 1);
        esrc[pos] = src[i];
    }
}

// ---------------- scaled GEMM: C[M,128] = diag(rinv) * A[M,K] @ W[K,128] -----
#define GBM 128
#define GBK 16

__global__ void __launch_bounds__(256)
gemm_scaled_kernel(const float* __restrict__ A, const float* __restrict__ W,
                   const float* __restrict__ rinv, float* __restrict__ C,
                   int M, int K) {
    __shared__ float As[GBK][GBM];
    __shared__ float Bs[GBK][HID];

    const int tid = threadIdx.x;          // 256
    const int tx  = tid & 15;             // 16 * 8 = 128 cols
    const int ty  = tid >> 4;             // 16 * 8 = 128 rows
    const int brow = blockIdx.x * GBM;

    // A-load mapping: 128x16 tile, each thread 8 consecutive k of one row
    const int ar = tid >> 1;              // 0..127
    const int ac = (tid & 1) * 8;
    const int gr = brow + ar;
    const bool rv = (gr < M);
    const float s = rv ? rinv[gr] : 0.0f;
    const float* Arow = A + (long)gr * K;

    // B-load mapping: 16x128 tile, 8 consecutive cols per thread
    const int br = tid >> 4;
    const int bc = (tid & 15) * 8;

    float acc[8][8];
#pragma unroll
    for (int i = 0; i < 8; ++i)
#pragma unroll
        for (int j = 0; j < 8; ++j) acc[i][j] = 0.0f;

    for (int k0 = 0; k0 < K; k0 += GBK) {
#pragma unroll
        for (int j = 0; j < 8; ++j) {
            int gk = k0 + ac + j;
            As[ac + j][ar] = (rv && gk < K) ? Arow[gk] * s : 0.0f;
        }
        {
            int gk = k0 + br;
            if (gk < K) {
                float4 w0 = *reinterpret_cast<const float4*>(&W[(long)gk * HID + bc]);
                float4 w1 = *reinterpret_cast<const float4*>(&W[(long)gk * HID + bc + 4]);
                *reinterpret_cast<float4*>(&Bs[br][bc])     = w0;
                *reinterpret_cast<float4*>(&Bs[br][bc + 4]) = w1;
            } else {
                float4 z = make_float4(0.f, 0.f, 0.f, 0.f);
                *reinterpret_cast<float4*>(&Bs[br][bc])     = z;
                *reinterpret_cast<float4*>(&Bs[br][bc + 4]) = z;
            }
        }
        __syncthreads();

#pragma unroll
        for (int kk = 0; kk < GBK; ++kk) {
            float a_[8], b_[8];
            *reinterpret_cast<float4*>(a_)     = *reinterpret_cast<const float4*>(&As[kk][ty * 8]);
            *reinterpret_cast<float4*>(a_ + 4) = *reinterpret_cast<const float4*>(&As[kk][ty * 8 + 4]);
            *reinterpret_cast<float4*>(b_)     = *reinterpret_cast<const float4*>(&Bs[kk][tx * 8]);
            *reinterpret_cast<float4*>(b_ + 4) = *reinterpret_cast<const float4*>(&Bs[kk][tx * 8 + 4]);
#pragma unroll
            for (int i = 0; i < 8; ++i)
#pragma unroll
                for (int j = 0; j < 8; ++j)
                    acc[i][j] = fmaf(a_[i], b_[j], acc[i][j]);
        }
        __syncthreads();
    }

#pragma unroll
    for (int i = 0; i < 8; ++i) {
        int grr = brow + ty * 8 + i;
        if (grr < M) {
            float4 v0 = make_float4(acc[i][0], acc[i][1], acc[i][2], acc[i][3]);
            float4 v1 = make_float4(acc[i][4], acc[i][5], acc[i][6], acc[i][7]);
            *reinterpret_cast<float4*>(&C[(long)grr * HID + tx * 8])     = v0;
            *reinterpret_cast<float4*>(&C[(long)grr * HID + tx * 8 + 4]) = v1;
        }
    }
}

// ---------------- gather + finalize: out = relu(rin * sum_{e->n} h[src] + b) -
__global__ void __launch_bounds__(256)
gather_kernel(const float* __restrict__ h, const int* __restrict__ esrc,
              const int* __restrict__ row_start, const float* __restrict__ rin,
              const float* __restrict__ b, float* __restrict__ out) {
    int w    = (blockIdx.x * blockDim.x + threadIdx.x) >> 5;  // node
    int lane = threadIdx.x & 31;
    if (w >= NN) return;
    int beg = row_start[w], end = row_start[w + 1];
    const float4* hv = reinterpret_cast<const float4*>(h);
    float4 acc = make_float4(0.f, 0.f, 0.f, 0.f);
    int p = beg;
    for (; p + 4 <= end; p += 4) {
        int s0 = esrc[p], s1 = esrc[p + 1], s2 = esrc[p + 2], s3 = esrc[p + 3];
        float4 v0 = hv[(long)s0 * 32 + lane];
        float4 v1 = hv[(long)s1 * 32 + lane];
        float4 v2 = hv[(long)s2 * 32 + lane];
        float4 v3 = hv[(long)s3 * 32 + lane];
        acc.x += (v0.x + v1.x) + (v2.x + v3.x);
        acc.y += (v0.y + v1.y) + (v2.y + v3.y);
        acc.z += (v0.z + v1.z) + (v2.z + v3.z);
        acc.w += (v0.w + v1.w) + (v2.w + v3.w);
    }
    for (; p < end; ++p) {
        int s = esrc[p];
        float4 v = hv[(long)s * 32 + lane];
        acc.x += v.x; acc.y += v.y; acc.z += v.z; acc.w += v.w;
    }
    float r = rin[w];
    float4 bb = reinterpret_cast<const float4*>(b)[lane];
    float4 o;
    o.x = fmaxf(fmaf(acc.x, r, bb.x), 0.0f);
    o.y = fmaxf(fmaf(acc.y, r, bb.y), 0.0f);
    o.z = fmaxf(fmaf(acc.z, r, bb.z), 0.0f);
    o.w = fmaxf(fmaf(acc.w, r, bb.w), 0.0f);
    reinterpret_cast<float4*>(out)[(long)w * 32 + lane] = o;
}

// ---------------- FC head: out = relu(x3 + x2) @ Wfc + bfc ------------------
__global__ void __launch_bounds__(256)
fc_kernel(const float* __restrict__ x3, const float* __restrict__ x2,
          const float* __restrict__ Wfc, const float* __restrict__ bfc,
          float* __restrict__ out) {
    __shared__ float Ws[HID * OUTF];  // 5248 floats = 21KB
    __shared__ float bs[64];
    int tid = threadIdx.x;
    for (int i = tid; i < HID * OUTF; i += 256) Ws[i] = Wfc[i];
    if (tid < OUTF) bs[tid] = bfc[tid];
    __syncthreads();

    int w    = blockIdx.x * 8 + (tid >> 5);
    int lane = tid & 31;
    if (w >= NN) return;

    float y[4];
#pragma unroll
    for (int c = 0; c < 4; ++c) {
        int k = c * 32 + lane;
        y[c] = fmaxf(x3[(long)w * HID + k] + x2[(long)w * HID + k], 0.0f);
    }
    float a0 = 0.0f, a1 = 0.0f;
#pragma unroll
    for (int c = 0; c < 4; ++c) {
#pragma unroll
        for (int kk = 0; kk < 32; ++kk) {
            float yv = __shfl_sync(0xffffffffu, y[c], kk);
            int k = c * 32 + kk;
            a0 = fmaf(yv, Ws[k * OUTF + lane], a0);
            if (lane < OUTF - 32) a1 = fmaf(yv, Ws[k * OUTF + 32 + lane], a1);
        }
    }
    out[(long)w * OUTF + lane] = a0 + bs[lane];
    if (lane < OUTF - 32)
        out[(long)w * OUTF + 32 + lane] = a1 + bs[32 + lane];
}

// ---------------- launcher ---------------------------------------------------
extern "C" void kernel_launch(void* const* d_in, const int* in_sizes, int n_in,
                              void* d_out, int out_size) {
    const float* feat = (const float*)d_in[0];
    const int*   src  = (const int*)  d_in[1];
    const int*   dst  = (const int*)  d_in[2];
    const float* W1   = (const float*)d_in[3];
    const float* b1   = (const float*)d_in[4];
    const float* W2   = (const float*)d_in[5];
    const float* b2   = (const float*)d_in[6];
    const float* W3   = (const float*)d_in[7];
    const float* b3   = (const float*)d_in[8];
    const float* Wfc  = (const float*)d_in[9];
    const float* bfc  = (const float*)d_in[10];
    float* out = (float*)d_out;

    float *h, *x1, *x2, *x3, *rout, *rin;
    int *cout_, *cin_, *cursor, *row_start, *esrc;
    cudaGetSymbolAddress((void**)&h,   g_h);
    cudaGetSymbolAddress((void**)&x1,  g_x1);
    cudaGetSymbolAddress((void**)&x2,  g_x2);
    cudaGetSymbolAddress((void**)&x3,  g_x3);
    cudaGetSymbolAddress((void**)&cout_, g_cnt_out);
    cudaGetSymbolAddress((void**)&cin_,  g_cnt_in);
    cudaGetSymbolAddress((void**)&cursor, g_cursor);
    cudaGetSymbolAddress((void**)&row_start, g_row_start);
    cudaGetSymbolAddress((void**)&esrc, g_esrc);
    cudaGetSymbolAddress((void**)&rout, g_rout);
    cudaGetSymbolAddress((void**)&rin,  g_rin);

    // ---- CSR build (per-launch; graph-capturable, stateless) ----
    cudaMemsetAsync(cout_,  0, NN * sizeof(int));
    cudaMemsetAsync(cin_,   0, NN * sizeof(int));
    cudaMemsetAsync(cursor, 0, NN * sizeof(int));
    count_kernel<<<(NE + 255) / 256, 256>>>(src, dst, cout_, cin_, NE);
    rinv_kernel<<<(NN + 255) / 256, 256>>>(cout_, cin_, rout, rin, NN);
    scan_kernel<<<1, 1024>>>(cin_, row_start);
    fill_kernel<<<(NE + 255) / 256, 256>>>(src, dst, row_start, cursor, esrc, NE);

    const int gemm_grid   = (NN + GBM - 1) / GBM;
    const int gather_grid = (NN * 32 + 255) / 256;

    // layer 1: 602 -> 128
    gemm_scaled_kernel<<<gemm_grid, 256>>>(feat, W1, rout, h, NN, INF);
    gather_kernel<<<gather_grid, 256>>>(h, esrc, row_start, rin, b1, x1);

    // layer 2: 128 -> 128 (reference computes it twice; x2 = both main & branch)
    gemm_scaled_kernel<<<gemm_grid, 256>>>(x1, W2, rout, h, NN, HID);
    gather_kernel<<<gather_grid, 256>>>(h, esrc, row_start, rin, b2, x2);

    // layer 3: 128 -> 128
    gemm_scaled_kernel<<<gemm_grid, 256>>>(x2, W3, rout, h, NN, HID);
    gather_kernel<<<gather_grid, 256>>>(h, esrc, row_start, rin, b3, x3);

    // FC head with fused residual relu
    fc_kernel<<<(NN + 7) / 8, 256>>>(x3, x2, Wfc, bfc, out);
}